// round 17
// baseline (speedup 1.0000x reference)
#include <cuda_runtime.h>

// logLikelihood_loss: sum over (B,T,P) of -log(clip(bivariate_gaussian_pdf, 1e-10)) / P
// B=64, T=128, P=512 -> 4,194,304 records. y_target: (...,3) f32, o_pred: (...,5) f32.
// HBM-bound streaming reduction. Log-domain formulation avoids exp/log round-trip.
//
// R16: one-wave grid (1184 = 148 SM x occ 8) grid-stride loop WITH
//      prefetch.global.L2 for iteration i+1 issued before iteration i's
//      compute. This is the piece R6 (28.7us: loads serialized behind compute)
//      and R14 (26.8us: occ 3) both lacked: prefetch costs no destination regs
//      and no dependency slot, keeps occ 8, feeds DRAM during compute, and
//      converts next iteration's LDGs into L2 hits (~234cyc vs 577). Warp-
//      coverage: thread t's o-base line floor(5t/8) covers lines 0..19 of the
//      warp region, y-base floor(3t/8) covers 0..11 -> 2 prefetches/thread.
//      No wave tail (grid == resident set); 3-vs-4-iter imbalance spreads at
//      warp granularity. Tail: R15's proven fire-and-forget RED + busy-poll.

#define N_ELEM   4194304
#define GROUPS   (N_ELEM / 4)          // 1,048,576 groups of 4 records
#define THREADS  256
#define GRID     (148 * 8)             // one full wave at occ=8
#define STRIDE   (GRID * THREADS)      // 303,104 threads

// Fixed-point packing: bits [0:51) = (v + BIAS)*2^32 summed, bits [51:64) = count.
// Per-block v = block_sum/512; block covers <= 4096 records -> |v| <= 184.2;
// BIAS=256 keeps it positive. Max: 1184*(256+185)*2^32 = 522144*2^32 < 2^51 ✓.
#define PACK_BIAS   256.0
#define PACK_SCALE  4294967296.0       // 2^32
#define CNT_SHIFT   51
#define SUM_MASK    ((1ULL << CNT_SHIFT) - 1)

__device__ unsigned long long g_pack = 0ULL;   // reset by spinner each run

// Accurate tanh from fast exp (independent of -use_fast_math's tanh.approx,
// whose abs error would poison 1-rho^2).
__device__ __forceinline__ float fast_tanh(float x) {
    float ax = fabsf(x);
    float e  = __expf(2.0f * ax);
    float t  = 1.0f - __fdividef(2.0f, e + 1.0f);
    return copysignf(t, x);
}

__global__ __launch_bounds__(THREADS, 8)   // keep <=32 regs -> occ 8
void nll_kernel(const float* __restrict__ y, const float* __restrict__ o,
                float* __restrict__ out) {
    const int t = threadIdx.x;

    const float LOG_2PI  = 1.8378770664093453f;   // ln(2*pi)
    const float CLAMP_HI = 23.025850929940457f;   // -ln(1e-10)

    float acc = 0.0f;

    for (int g = blockIdx.x * THREADS + t; g < GROUPS; g += STRIDE) {
        const float4* o4 = reinterpret_cast<const float4*>(o) + (size_t)g * 5;
        const float4* y4 = reinterpret_cast<const float4*>(y) + (size_t)g * 3;

        // Prefetch next iteration's lines to L2 BEFORE this iteration's
        // compute: fire-and-forget, no regs, keeps DRAM fed during compute.
        if (g + STRIDE < GROUPS) {
            asm volatile("prefetch.global.L2 [%0];"
                         :: "l"(o4 + (size_t)STRIDE * 5) : "memory");
            asm volatile("prefetch.global.L2 [%0];"
                         :: "l"(y4 + (size_t)STRIDE * 3) : "memory");
        }

        float of[20], yf[12];
#pragma unroll
        for (int k = 0; k < 5; k++) reinterpret_cast<float4*>(of)[k] = o4[k];
#pragma unroll
        for (int k = 0; k < 3; k++) reinterpret_cast<float4*>(yf)[k] = y4[k];

#pragma unroll
        for (int j = 0; j < 4; j++) {
            float mux = of[5 * j + 0];
            float muy = of[5 * j + 1];
            float lsx = of[5 * j + 2];   // log(sx)
            float lsy = of[5 * j + 3];   // log(sy)
            float cra = of[5 * j + 4];   // pre-tanh corr

            float y1 = yf[3 * j + 1];
            float y2 = yf[3 * j + 2];

            float inv_sx = __expf(-lsx);
            float inv_sy = __expf(-lsy);
            float nx = (y1 - mux) * inv_sx;
            float ny = (y2 - muy) * inv_sy;

            float tt = fast_tanh(cra);
            float om = fmaf(-tt, tt, 1.0f);            // 1 - rho^2 > 0
            float z  = fmaf(nx, nx, fmaf(ny, ny, -2.0f * tt * nx * ny));

            // -log pdf = z/(2*om) + log(2pi) + log(sx) + log(sy) + 0.5*log(om)
            float nll = 0.5f * __fdividef(z, om)
                      + (LOG_2PI + lsx + lsy + 0.5f * __logf(om));
            acc += fminf(nll, CLAMP_HI);               // == -log(clip(pdf,1e-10))
        }
    }

    // ── Block reduction ───────────────────────────────────────────────────
#pragma unroll
    for (int off = 16; off; off >>= 1)
        acc += __shfl_down_sync(0xffffffffu, acc, off);

    __shared__ float wsum[THREADS / 32];
    const int lane = t & 31;
    const int wid  = t >> 5;
    if (lane == 0) wsum[wid] = acc;
    __syncthreads();

    if (wid == 0) {
        float v = (lane < THREADS / 32) ? wsum[lane] : 0.0f;
#pragma unroll
        for (int off = 4; off; off >>= 1)
            v += __shfl_down_sync(0xffffffffu, v, off);

        if (lane == 0) {
            // Fire-and-forget RED of the packed contribution: no return trip,
            // block exits immediately.
            double vb = (double)(v * (1.0f / 512.0f)) + PACK_BIAS;
            unsigned long long pack =
                (1ULL << CNT_SHIFT) | (unsigned long long)llrint(vb * PACK_SCALE);
            asm volatile("red.relaxed.gpu.global.add.u64 [%0], %1;"
                         :: "l"(&g_pack), "l"(pack) : "memory");

            // ── Spinner: one thread of block 0, pure atomic busy-poll ─────
            if (blockIdx.x == 0) {
                unsigned long long cur;
                do {
                    asm volatile("atom.relaxed.gpu.global.add.u64 %0, [%1], %2;"
                                 : "=l"(cur) : "l"(&g_pack), "l"(0ULL) : "memory");
                } while ((cur >> CNT_SHIFT) != (unsigned long long)GRID);

                double s = (double)(cur & SUM_MASK) * (1.0 / PACK_SCALE)
                         - PACK_BIAS * (double)GRID;
                out[0] = (float)s;
                atomicExch(&g_pack, 0ULL);   // reset for next graph replay
            }
        }
    }
}

extern "C" void kernel_launch(void* const* d_in, const int* in_sizes, int n_in,
                              void* d_out, int out_size) {
    const float* y = (const float*)d_in[0];   // y_target, 12,582,912 floats
    const float* o = (const float*)d_in[1];   // o_pred,  20,971,520 floats
    float* out = (float*)d_out;               // scalar fp32

    nll_kernel<<<GRID, THREADS>>>(y, o, out);
}